// round 2
// baseline (speedup 1.0000x reference)
#include <cuda_runtime.h>

// Problem constants (fixed by the reference)
#define D_   24
#define NK_  2
#define F_   (NK_ * D_)   // 48
#define H_   64
#define DEG_ 32
#define WPB  8            // warps (nodes) per block
#define TPB  (WPB * 32)

__global__ __launch_bounds__(TPB) void gnn_fused_kernel(
    const float* __restrict__ x,        // [N, 24]
    const int* __restrict__ edge_idx,   // [2, E] int32; src = first E entries
    const float* __restrict__ kvals,    // [2, E]
    const float* __restrict__ W,        // [64, 48] row-major
    float* __restrict__ out,            // [N, 64]
    int N, int E)
{
    __shared__ float Wt[F_ * H_];       // W transposed: Wt[j*64 + h], 12 KB
    __shared__ float feat[WPB][F_];

    // Cooperatively load W transposed (conflict-free consumption later:
    // lane l reads Wt[j*64 + l] -> bank = l).
    for (int idx = threadIdx.x; idx < H_ * F_; idx += TPB) {
        int h = idx / F_;
        int j = idx - h * F_;
        Wt[j * H_ + h] = W[idx];
    }
    __syncthreads();

    const int warp = threadIdx.x >> 5;
    const int lane = threadIdx.x & 31;
    const int node = blockIdx.x * WPB + warp;
    if (node >= N) return;

    const long long ebase = (long long)node * DEG_;

    // Per-lane edge metadata: lane l owns edge ebase + l (coalesced loads).
    const int   s_mine  = edge_idx[ebase + lane];
    const float k0_mine = kvals[ebase + lane];
    const float k1_mine = kvals[(long long)E + ebase + lane];

    float acc0 = 0.f, acc1 = 0.f, sumx = 0.f;

    // Lanes 0..23 each own one feature dim; broadcast edge data via shuffle.
    // Fully unrolled: 32 independent 96B row gathers in flight per warp.
    #pragma unroll
    for (int e = 0; e < DEG_; ++e) {
        const int   se = __shfl_sync(0xffffffffu, s_mine,  e);
        const float k0 = __shfl_sync(0xffffffffu, k0_mine, e);
        const float k1 = __shfl_sync(0xffffffffu, k1_mine, e);
        float xv = 0.f;
        if (lane < D_) xv = __ldg(&x[(long long)se * D_ + lane]);
        acc0 = fmaf(k0, xv, acc0);
        acc1 = fmaf(k1, xv, acc1);
        sumx += xv;
    }

    if (lane < D_) {
        const float xi = x[(long long)node * D_ + lane];
        const float m  = sumx * (1.0f / DEG_);
        feat[warp][lane]      = acc0 - m + xi;
        feat[warp][D_ + lane] = acc1 - m + xi;
    }
    __syncwarp();

    // 48 -> 64 linear: lane l computes output channels l and l+32.
    float y0 = 0.f, y1 = 0.f;
    #pragma unroll
    for (int j = 0; j < F_; ++j) {
        const float f = feat[warp][j];         // broadcast (no conflict)
        y0 = fmaf(f, Wt[j * H_ + lane],      y0);
        y1 = fmaf(f, Wt[j * H_ + lane + 32], y1);
    }

    float* orow = out + (long long)node * H_;
    orow[lane]      = y0;
    orow[lane + 32] = y1;
}

extern "C" void kernel_launch(void* const* d_in, const int* in_sizes, int n_in,
                              void* d_out, int out_size) {
    const float* x    = (const float*)d_in[0];      // [N, 24]
    const int*   eidx = (const int*)d_in[1];        // [2, E] int32
    const float* kv   = (const float*)d_in[2];      // [2, E]
    const float* W    = (const float*)d_in[3];      // [64, 48]
    float*       out  = (float*)d_out;

    const int N = in_sizes[0] / D_;
    const int E = in_sizes[2] / NK_;

    const int blocks = (N + WPB - 1) / WPB;
    gnn_fused_kernel<<<blocks, TPB>>>(x, eidx, kv, W, out, N, E);
}

// round 3
// speedup vs baseline: 1.3359x; 1.3359x over previous
#include <cuda_runtime.h>

#define D_   24
#define NK_  2
#define F_   (NK_ * D_)   // 48
#define H_   64
#define DEG_ 32
#define WPB  16           // warps (nodes) per block
#define TPB  (WPB * 32)   // 512

__global__ __launch_bounds__(TPB) void gnn_fused_kernel(
    const float* __restrict__ x,        // [N, 24]
    const int* __restrict__ edge_idx,   // [2, E] int32; src = first E entries
    const float* __restrict__ kvals,    // [2, E]
    const float* __restrict__ W,        // [64, 48] row-major
    float* __restrict__ out,            // [N, 64]
    int N, int E)
{
    // Wq[p][l] = {W[2l][2p], W[2l+1][2p], W[2l][2p+1], W[2l+1][2p+1]}
    __shared__ float4 Wq[24 * 32];        // 12 KB
    __shared__ int    soff[WPB][DEG_];    // 2 KB  (src * 96 byte offsets)
    __shared__ float2 skk[WPB][DEG_];     // 4 KB  (k0, k1 per edge)
    __shared__ float  feat[WPB][F_];      // 3 KB

    const int tid  = threadIdx.x;
    const int warp = tid >> 5;
    const int lane = tid & 31;
    const int node = blockIdx.x * WPB + warp;

    // Stage W repacked (each element read once per block)
    for (int idx = tid; idx < 24 * 32; idx += TPB) {
        const int p = idx >> 5, l = idx & 31, j = p * 2;
        Wq[idx] = make_float4(W[(2 * l) * F_ + j],     W[(2 * l + 1) * F_ + j],
                              W[(2 * l) * F_ + j + 1], W[(2 * l + 1) * F_ + j + 1]);
    }

    // Stage edge metadata: thread t owns edge t of this block's 512 edges
    const long long geb = (long long)blockIdx.x * (WPB * DEG_) + tid;
    if (node < N) {
        soff[warp][lane] = edge_idx[geb] * 96;   // byte offset of row
        skk[warp][lane]  = make_float2(kvals[geb], kvals[geb + (long long)E]);
    }
    __syncthreads();
    if (node >= N) return;

    const bool  pred  = lane < D_;
    const char* xlane = (const char*)(x + lane);
    const float xi    = pred ? x[(long long)node * D_ + lane] : 0.f;

    float acc0 = 0.f, acc1 = 0.f, sumx = 0.f;

    // 4 chunks of 8 edges: batch 8 gathers (MLP=8), then FMA
    #pragma unroll
    for (int c = 0; c < 4; ++c) {
        const int4 oa = *(const int4*)&soff[warp][c * 8];
        const int4 ob = *(const int4*)&soff[warp][c * 8 + 4];
        float xv[8];
        xv[0] = pred ? __ldg((const float*)(xlane + oa.x)) : 0.f;
        xv[1] = pred ? __ldg((const float*)(xlane + oa.y)) : 0.f;
        xv[2] = pred ? __ldg((const float*)(xlane + oa.z)) : 0.f;
        xv[3] = pred ? __ldg((const float*)(xlane + oa.w)) : 0.f;
        xv[4] = pred ? __ldg((const float*)(xlane + ob.x)) : 0.f;
        xv[5] = pred ? __ldg((const float*)(xlane + ob.y)) : 0.f;
        xv[6] = pred ? __ldg((const float*)(xlane + ob.z)) : 0.f;
        xv[7] = pred ? __ldg((const float*)(xlane + ob.w)) : 0.f;

        const float4 kA = *(const float4*)&skk[warp][c * 8];      // edges 0,1
        const float4 kB = *(const float4*)&skk[warp][c * 8 + 2];  // edges 2,3
        const float4 kC = *(const float4*)&skk[warp][c * 8 + 4];  // edges 4,5
        const float4 kD = *(const float4*)&skk[warp][c * 8 + 6];  // edges 6,7

        acc0 = fmaf(kA.x, xv[0], acc0); acc1 = fmaf(kA.y, xv[0], acc1); sumx += xv[0];
        acc0 = fmaf(kA.z, xv[1], acc0); acc1 = fmaf(kA.w, xv[1], acc1); sumx += xv[1];
        acc0 = fmaf(kB.x, xv[2], acc0); acc1 = fmaf(kB.y, xv[2], acc1); sumx += xv[2];
        acc0 = fmaf(kB.z, xv[3], acc0); acc1 = fmaf(kB.w, xv[3], acc1); sumx += xv[3];
        acc0 = fmaf(kC.x, xv[4], acc0); acc1 = fmaf(kC.y, xv[4], acc1); sumx += xv[4];
        acc0 = fmaf(kC.z, xv[5], acc0); acc1 = fmaf(kC.w, xv[5], acc1); sumx += xv[5];
        acc0 = fmaf(kD.x, xv[6], acc0); acc1 = fmaf(kD.y, xv[6], acc1); sumx += xv[6];
        acc0 = fmaf(kD.z, xv[7], acc0); acc1 = fmaf(kD.w, xv[7], acc1); sumx += xv[7];
    }

    const float m = sumx * (1.0f / DEG_);
    if (pred) {
        feat[warp][lane]      = acc0 - m + xi;
        feat[warp][lane + D_] = acc1 - m + xi;
    }
    __syncwarp();

    // 48 -> 64 linear: lane l computes output channels 2l, 2l+1
    float y0 = 0.f, y1 = 0.f;
    #pragma unroll
    for (int j = 0; j < F_; j += 4) {
        const float4 f  = *(const float4*)&feat[warp][j];     // broadcast
        const float4 wa = Wq[(j >> 1) * 32 + lane];           // dims j, j+1
        const float4 wb = Wq[((j >> 1) + 1) * 32 + lane];     // dims j+2, j+3
        y0 = fmaf(f.x, wa.x, y0); y1 = fmaf(f.x, wa.y, y1);
        y0 = fmaf(f.y, wa.z, y0); y1 = fmaf(f.y, wa.w, y1);
        y0 = fmaf(f.z, wb.x, y0); y1 = fmaf(f.z, wb.y, y1);
        y0 = fmaf(f.w, wb.z, y0); y1 = fmaf(f.w, wb.w, y1);
    }

    *(float2*)(out + (long long)node * H_ + lane * 2) = make_float2(y0, y1);
}

extern "C" void kernel_launch(void* const* d_in, const int* in_sizes, int n_in,
                              void* d_out, int out_size) {
    const float* x    = (const float*)d_in[0];      // [N, 24]
    const int*   eidx = (const int*)d_in[1];        // [2, E] int32
    const float* kv   = (const float*)d_in[2];      // [2, E]
    const float* W    = (const float*)d_in[3];      // [64, 48]
    float*       out  = (float*)d_out;

    const int N = in_sizes[0] / D_;
    const int E = in_sizes[2] / NK_;

    const int blocks = (N + WPB - 1) / WPB;
    gnn_fused_kernel<<<blocks, TPB>>>(x, eidx, kv, W, out, N, E);
}

// round 4
// speedup vs baseline: 3.1315x; 2.3441x over previous
#include <cuda_runtime.h>

#define D_   24
#define F_   48           // NK*D
#define H_   64
#define DEG_ 32
#define NW   8            // warps per block
#define NPW  8            // nodes per warp (sequential rounds)
#define NPB  (NW * NPW)   // 64 nodes per block
#define TPB  (NW * 32)    // 256 threads
#define FS   12           // featW g-stride (pad: 3-way max STS conflict, float4-aligned reads)
#define WS   65           // Wt h-stride (conflict-free transpose store + read)

__global__ __launch_bounds__(TPB, 4) void gnn_fused_kernel(
    const float* __restrict__ x,        // [N, 24]
    const int* __restrict__ edge_idx,   // [2, E] int32; src = first E
    const float* __restrict__ kvals,    // [2, E]
    const float* __restrict__ W,        // [64, 48] row-major
    float* __restrict__ out,            // [N, 64]
    int N, int E)
{
    __shared__ float  Wt[F_ * WS];            // 12.2 KB, Wt[j*65+h] = W[h][j]
    __shared__ float  featW[NW][F_ * FS];     // 18 KB, warp-private featW[w][j*12+g]
    __shared__ int    soff[NW][DEG_];         // 1 KB
    __shared__ float2 skk[NW][DEG_];          // 2 KB

    const int tid  = threadIdx.x;
    const int w    = tid >> 5;
    const int lane = tid & 31;

    // Stage W transposed (coalesced LDG, conflict-free STS via stride-65)
    for (int idx = tid; idx < H_ * F_; idx += TPB) {
        const int h = idx / F_, j = idx - h * F_;
        Wt[j * WS + h] = W[idx];
    }
    // (no sync yet — Wt only needed after gather; sync below overlaps latency)

    const int  base  = blockIdx.x * NPB + w * NPW;
    const bool pred  = lane < D_;
    const char* xlane = (const char*)(x + lane);

    // ---- Gather phase: 8 sequential nodes per warp, warp-private staging ----
    #pragma unroll 1
    for (int r = 0; r < NPW; ++r) {
        const int  node  = base + r;
        const bool valid = node < N;
        if (valid) {
            const int e = node * DEG_ + lane;
            soff[w][lane] = edge_idx[e] * 96;                       // row byte offset
            skk[w][lane]  = make_float2(kvals[e], kvals[e + E]);
        }
        __syncwarp();

        const bool act = pred && valid;
        const float xi = act ? x[node * D_ + lane] : 0.f;
        float acc0 = 0.f, acc1 = 0.f, sumx = 0.f;

        #pragma unroll
        for (int c = 0; c < 4; ++c) {
            const int4 oa = *(const int4*)&soff[w][c * 8];
            const int4 ob = *(const int4*)&soff[w][c * 8 + 4];
            float xv[8];
            xv[0] = act ? __ldg((const float*)(xlane + oa.x)) : 0.f;
            xv[1] = act ? __ldg((const float*)(xlane + oa.y)) : 0.f;
            xv[2] = act ? __ldg((const float*)(xlane + oa.z)) : 0.f;
            xv[3] = act ? __ldg((const float*)(xlane + oa.w)) : 0.f;
            xv[4] = act ? __ldg((const float*)(xlane + ob.x)) : 0.f;
            xv[5] = act ? __ldg((const float*)(xlane + ob.y)) : 0.f;
            xv[6] = act ? __ldg((const float*)(xlane + ob.z)) : 0.f;
            xv[7] = act ? __ldg((const float*)(xlane + ob.w)) : 0.f;

            const float4 kA = *(const float4*)&skk[w][c * 8];      // edges 0,1
            const float4 kB = *(const float4*)&skk[w][c * 8 + 2];  // edges 2,3
            const float4 kC = *(const float4*)&skk[w][c * 8 + 4];  // edges 4,5
            const float4 kD = *(const float4*)&skk[w][c * 8 + 6];  // edges 6,7

            acc0 = fmaf(kA.x, xv[0], acc0); acc1 = fmaf(kA.y, xv[0], acc1); sumx += xv[0];
            acc0 = fmaf(kA.z, xv[1], acc0); acc1 = fmaf(kA.w, xv[1], acc1); sumx += xv[1];
            acc0 = fmaf(kB.x, xv[2], acc0); acc1 = fmaf(kB.y, xv[2], acc1); sumx += xv[2];
            acc0 = fmaf(kB.z, xv[3], acc0); acc1 = fmaf(kB.w, xv[3], acc1); sumx += xv[3];
            acc0 = fmaf(kC.x, xv[4], acc0); acc1 = fmaf(kC.y, xv[4], acc1); sumx += xv[4];
            acc0 = fmaf(kC.z, xv[5], acc0); acc1 = fmaf(kC.w, xv[5], acc1); sumx += xv[5];
            acc0 = fmaf(kD.x, xv[6], acc0); acc1 = fmaf(kD.y, xv[6], acc1); sumx += xv[6];
            acc0 = fmaf(kD.z, xv[7], acc0); acc1 = fmaf(kD.w, xv[7], acc1); sumx += xv[7];
        }

        if (pred) {
            const float m = sumx * (1.0f / DEG_);
            featW[w][lane * FS + r]        = acc0 - m + xi;   // feature j=lane
            featW[w][(lane + D_) * FS + r] = acc1 - m + xi;   // feature j=lane+24
        }
        __syncwarp();   // protect soff/skk before next round restages
    }

    __syncthreads();    // Wt visible to all warps

    // ---- Epilogue: one W pass serves 8 nodes per warp ----
    float y0[NPW], y1[NPW];
    #pragma unroll
    for (int g = 0; g < NPW; ++g) { y0[g] = 0.f; y1[g] = 0.f; }

    #pragma unroll
    for (int j = 0; j < F_; ++j) {
        const float w0 = Wt[j * WS + lane];        // conflict-free
        const float w1 = Wt[j * WS + lane + 32];
        const float4 fa = *(const float4*)&featW[w][j * FS];      // broadcast g=0..3
        const float4 fb = *(const float4*)&featW[w][j * FS + 4];  // broadcast g=4..7
        y0[0] = fmaf(fa.x, w0, y0[0]); y1[0] = fmaf(fa.x, w1, y1[0]);
        y0[1] = fmaf(fa.y, w0, y0[1]); y1[1] = fmaf(fa.y, w1, y1[1]);
        y0[2] = fmaf(fa.z, w0, y0[2]); y1[2] = fmaf(fa.z, w1, y1[2]);
        y0[3] = fmaf(fa.w, w0, y0[3]); y1[3] = fmaf(fa.w, w1, y1[3]);
        y0[4] = fmaf(fb.x, w0, y0[4]); y1[4] = fmaf(fb.x, w1, y1[4]);
        y0[5] = fmaf(fb.y, w0, y0[5]); y1[5] = fmaf(fb.y, w1, y1[5]);
        y0[6] = fmaf(fb.z, w0, y0[6]); y1[6] = fmaf(fb.z, w1, y1[6]);
        y0[7] = fmaf(fb.w, w0, y0[7]); y1[7] = fmaf(fb.w, w1, y1[7]);
    }

    #pragma unroll
    for (int g = 0; g < NPW; ++g) {
        const int node = base + g;
        if (node < N) {
            out[node * H_ + lane]      = y0[g];
            out[node * H_ + lane + 32] = y1[g];
        }
    }
}

extern "C" void kernel_launch(void* const* d_in, const int* in_sizes, int n_in,
                              void* d_out, int out_size) {
    const float* x    = (const float*)d_in[0];      // [N, 24]
    const int*   eidx = (const int*)d_in[1];        // [2, E] int32
    const float* kv   = (const float*)d_in[2];      // [2, E]
    const float* W    = (const float*)d_in[3];      // [64, 48]
    float*       out  = (float*)d_out;

    const int N = in_sizes[0] / D_;
    const int E = in_sizes[2] / 2;

    const int blocks = (N + NPB - 1) / NPB;
    gnn_fused_kernel<<<blocks, TPB>>>(x, eidx, kv, W, out, N, E);
}